// round 11
// baseline (speedup 1.0000x reference)
#include <cuda_runtime.h>
#include <math.h>

// Problem constants (fixed shapes for this problem)
#define BGRAPHS 1024
#define TSTEPS  64
#define HDIM    512
#define H3      1536
#define EEDGES  200000

#define GPB     8                  // graphs per block
#define NBLOCKS (BGRAPHS / GPB)    // 128
#define NTHREADS 256
#define KT      8                  // k-tile (double-buffered)
#define NTILES  (HDIM / KT)        // 64 tiles per pass
#define WPITCH  12                 // floats per row: 48B, 16B-aligned, LDS.128 conflict-free

struct Smem {
    float wbuf[2][H3 * WPITCH];  // double-buffered weight tiles: [j][0..7]+pad
    float h[GPB][HDIM];          // recurrent state
    float x[GPB][HDIM];          // gathered edge tokens
    float bi[H3];
    float bh[H3];
    float lnw[HDIM];
    float lnb[HDIM];
    int   done[GPB];
    int   active[GPB];
    int   xidx[GPB];
    int   stopi[GPB];
};

__device__ __forceinline__ float warp_sum(float v) {
    #pragma unroll
    for (int o = 16; o > 0; o >>= 1) v += __shfl_xor_sync(0xFFFFFFFFu, v, o);
    return v;
}

__device__ __forceinline__ float sigmoidf_(float x) {
    return 1.0f / (1.0f + expf(-x));
}

// ---- packed fp32x2 helpers (sm_103a; ptxas never emits FFMA2 from C++) ----
__device__ __forceinline__ unsigned long long pack2(float lo, float hi) {
    unsigned long long r;
    asm("mov.b64 %0, {%1, %2};" : "=l"(r) : "f"(lo), "f"(hi));
    return r;
}
__device__ __forceinline__ void unpack2(unsigned long long v, float& lo, float& hi) {
    asm("mov.b64 {%0, %1}, %2;" : "=f"(lo), "=f"(hi) : "l"(v));
}
__device__ __forceinline__ void fma2(unsigned long long& acc,
                                     unsigned long long w2,
                                     unsigned long long a2) {
    // two independent IEEE fp32 fma.rn — bit-identical to the scalar pair
    asm("fma.rn.f32x2 %0, %1, %2, %0;" : "+l"(acc) : "l"(w2), "l"(a2));
}

// ---- cp.async helpers ----
__device__ __forceinline__ void cpasync16(void* smem_dst, const void* gsrc) {
    unsigned u = (unsigned)__cvta_generic_to_shared(smem_dst);
    asm volatile("cp.async.cg.shared.global [%0], [%1], 16;"
                 :: "r"(u), "l"(gsrc) : "memory");
}
__device__ __forceinline__ void cpasync_commit() {
    asm volatile("cp.async.commit_group;" ::: "memory");
}
template <int N>
__device__ __forceinline__ void cpasync_wait() {
    asm volatile("cp.async.wait_group %0;" :: "n"(N) : "memory");
}

// Issue cp.async stage of tile `ti` (k-range [ti*KT, ti*KT+8)) into wbuf[buf].
// Each thread copies 12 float4's: idx = tid + 256*r over 3072 quads,
// j = idx>>1 (row), q = idx&1 (which float4 of the 8-float row).
__device__ __forceinline__ void stage_tile(const float* __restrict__ Wg,
                                           float* wbuf, int ti, int tid) {
    const int kt = ti * KT;
    #pragma unroll
    for (int r = 0; r < 12; r++) {
        int idx = tid + NTHREADS * r;    // 0..3071
        int j = idx >> 1;
        int q = idx & 1;
        cpasync16(wbuf + j * WPITCH + 4 * q,
                  Wg + (size_t)j * HDIM + kt + 4 * q);
    }
    cpasync_commit();
}

// Compute one KT=8 tile from wbuf into packed accumulators.
__device__ __forceinline__ void compute_tile(const float* __restrict__ Ws,
                                             const float* __restrict__ As,
                                             unsigned long long accp[6][GPB / 2],
                                             int kt, int tid) {
    #pragma unroll
    for (int k4 = 0; k4 < 2; k4++) {
        // A values: broadcast float4 per graph
        float4 a4[GPB];
        #pragma unroll
        for (int g = 0; g < GPB; g++)
            a4[g] = *(const float4*)(As + g * HDIM + kt + 4 * k4);
        // W values: 4 consecutive k for each of this thread's 6 rows (LDS.128)
        float4 w4[6];
        #pragma unroll
        for (int jj = 0; jj < 6; jj++)
            w4[jj] = *(const float4*)(Ws + (tid + NTHREADS * jj) * WPITCH + 4 * k4);
        #pragma unroll
        for (int kk = 0; kk < 4; kk++) {
            unsigned long long ap[GPB / 2];
            #pragma unroll
            for (int p = 0; p < GPB / 2; p++) {
                float a0 = (kk == 0) ? a4[2*p].x   : (kk == 1) ? a4[2*p].y
                         : (kk == 2) ? a4[2*p].z   : a4[2*p].w;
                float a1 = (kk == 0) ? a4[2*p+1].x : (kk == 1) ? a4[2*p+1].y
                         : (kk == 2) ? a4[2*p+1].z : a4[2*p+1].w;
                ap[p] = pack2(a0, a1);
            }
            #pragma unroll
            for (int jj = 0; jj < 6; jj++) {
                float w = (kk == 0) ? w4[jj].x : (kk == 1) ? w4[jj].y
                        : (kk == 2) ? w4[jj].z : w4[jj].w;
                const unsigned long long w2 = pack2(w, w);
                #pragma unroll
                for (int p = 0; p < GPB / 2; p++)
                    fma2(accp[jj][p], w2, ap[p]);
            }
        }
    }
}

// Full pass over K with cp.async double buffering. Uniform for the block.
__device__ __forceinline__ void gemm_pass(const float* __restrict__ Wg,
                                          const float* As,
                                          unsigned long long accp[6][GPB / 2],
                                          Smem& S, int tid) {
    stage_tile(Wg, S.wbuf[0], 0, tid);     // prologue
    #pragma unroll 1
    for (int i = 0; i < NTILES; i++) {
        if (i + 1 < NTILES) {
            stage_tile(Wg, S.wbuf[(i + 1) & 1], i + 1, tid);
            cpasync_wait<1>();             // tile i complete
        } else {
            cpasync_wait<0>();
        }
        __syncthreads();                   // all threads' copies of tile i visible
        compute_tile(S.wbuf[i & 1], As, accp, i * KT, tid);
        __syncthreads();                   // block done reading buf before reuse
    }
}

__global__ void __launch_bounds__(NTHREADS, 1)
traj_encoder_kernel(const int*   __restrict__ actions,      // [B,T]
                    const float* __restrict__ edge_tokens,  // [E,H]
                    const int*   __restrict__ stop_indices, // [B]
                    const float* __restrict__ question,     // [B,H]
                    const float* __restrict__ node_tokens,  // [N,H]
                    const int*   __restrict__ start_locals, // [B*K]
                    const int*   __restrict__ start_ptr,    // [B+1]
                    const float* __restrict__ w_ih,         // [3H,H]
                    const float* __restrict__ w_hh,         // [3H,H]
                    const float* __restrict__ b_ih,         // [3H]
                    const float* __restrict__ b_hh,         // [3H]
                    const float* __restrict__ ln_w,         // [H]
                    const float* __restrict__ ln_b,         // [H]
                    float*       __restrict__ out)          // [B,T,H]
{
    extern __shared__ char smem_raw[];
    Smem& S = *reinterpret_cast<Smem*>(smem_raw);

    const int tid  = threadIdx.x;
    const int wid  = tid >> 5;
    const int lane = tid & 31;
    const int gbase = blockIdx.x * GPB;

    // ---- init: constants into smem ----
    for (int i = tid; i < H3; i += NTHREADS) { S.bi[i] = b_ih[i]; S.bh[i] = b_hh[i]; }
    for (int i = tid; i < HDIM; i += NTHREADS) { S.lnw[i] = ln_w[i]; S.lnb[i] = ln_b[i]; }
    if (tid < GPB) {
        S.done[tid]  = 0;
        S.stopi[tid] = stop_indices[gbase + tid];
    }

    // ---- h0: warp `wid` handles graph g = wid ----
    {
        const int g = wid;
        const int b = gbase + g;
        const int p0 = start_ptr[b];
        const int p1 = start_ptr[b + 1];
        const int cnt = p1 - p0;
        const float inv_den = 1.0f / (float)max(cnt, 1);
        float v[16];
        #pragma unroll
        for (int i = 0; i < 16; i++) {
            const int c = lane + 32 * i;
            float s = 0.0f;
            for (int p = p0; p < p1; p++) {
                int node = start_locals[p];
                s += node_tokens[(size_t)node * HDIM + c];
            }
            v[i] = question[(size_t)b * HDIM + c] + s * inv_den;
        }
        float s = 0.0f;
        #pragma unroll
        for (int i = 0; i < 16; i++) s += v[i];
        s = warp_sum(s);
        const float m = s * (1.0f / HDIM);
        float q = 0.0f;
        #pragma unroll
        for (int i = 0; i < 16; i++) { float d = v[i] - m; q += d * d; }
        q = warp_sum(q);
        const float inv = rsqrtf(q * (1.0f / HDIM) + 1e-5f);
        #pragma unroll
        for (int i = 0; i < 16; i++) {
            const int c = lane + 32 * i;
            S.h[g][c] = (v[i] - m) * inv * ln_w[c] + ln_b[c];
        }
    }
    __syncthreads();

    // ---- time loop ----
    #pragma unroll 1
    for (int t = 0; t < TSTEPS; t++) {
        // Phase 1: emit emb = LayerNorm(h) (before update), warp per graph
        {
            const int g = wid;
            const int b = gbase + g;
            float v[16];
            #pragma unroll
            for (int i = 0; i < 16; i++) v[i] = S.h[g][lane + 32 * i];
            float s = 0.0f;
            #pragma unroll
            for (int i = 0; i < 16; i++) s += v[i];
            s = warp_sum(s);
            const float m = s * (1.0f / HDIM);
            float q = 0.0f;
            #pragma unroll
            for (int i = 0; i < 16; i++) { float d = v[i] - m; q += d * d; }
            q = warp_sum(q);
            const float inv = rsqrtf(q * (1.0f / HDIM) + 1e-5f);
            float* o = out + ((size_t)b * TSTEPS + t) * HDIM;
            #pragma unroll
            for (int i = 0; i < 16; i++) {
                const int c = lane + 32 * i;
                o[c] = (v[i] - m) * inv * S.lnw[c] + S.lnb[c];
            }
        }

        // Phase 2: per-graph flags
        int actflag = 0;
        if (tid < GPB) {
            const int g = tid;
            const int b = gbase + g;
            const int a = actions[(size_t)b * TSTEPS + t];
            const bool is_stop = (a == S.stopi[g]) || (a < 0);
            const int act = (!S.done[g]) && (!is_stop);
            S.active[g] = act;
            S.done[g]   = S.done[g] || is_stop;
            int idx = a; if (idx < 0) idx = 0; if (idx > EEDGES - 1) idx = EEDGES - 1;
            S.xidx[g]   = idx;
            actflag = act;
        }
        const int anyact = __syncthreads_or(actflag);

        if (anyact) {
            // gather x rows (valid clipped index even for inactive graphs)
            #pragma unroll
            for (int r = 0; r < 4; r++) {
                const int q = tid + NTHREADS * r;     // 0..1023 quads
                const int g = q >> 7;
                const int off = (q & 127) * 4;
                *(float4*)&S.x[g][off] =
                    *(const float4*)(edge_tokens + (size_t)S.xidx[g] * HDIM + off);
            }
            __syncthreads();   // gather + flags visible before GEMM reads

            unsigned long long aip[6][GPB / 2];
            unsigned long long ahp[6][GPB / 2];
            #pragma unroll
            for (int jj = 0; jj < 6; jj++)
                #pragma unroll
                for (int p = 0; p < GPB / 2; p++) { aip[jj][p] = 0ull; ahp[jj][p] = 0ull; }

            gemm_pass(w_ih, &S.x[0][0], aip, S, tid);
            gemm_pass(w_hh, &S.h[0][0], ahp, S, tid);
            // gemm_pass ends with __syncthreads -> all S.h reads complete

            // unpack packed accumulators -> per-graph floats
            float ai[6][GPB], ah[6][GPB];
            #pragma unroll
            for (int jj = 0; jj < 6; jj++)
                #pragma unroll
                for (int p = 0; p < GPB / 2; p++) {
                    unpack2(aip[jj][p], ai[jj][2*p], ai[jj][2*p+1]);
                    unpack2(ahp[jj][p], ah[jj][2*p], ah[jj][2*p+1]);
                }

            // Phase 3: GRU update. Thread owns channels c = tid and c = tid+256.
            // jj mapping: j = tid + 256*jj  ->  c=tid uses jj {0,2,4}; c=tid+256 uses {1,3,5}
            #pragma unroll
            for (int cc = 0; cc < 2; cc++) {
                const int c = tid + NTHREADS * cc;
                const int jr = cc, jz = cc + 2, jn = cc + 4;
                const float bir = S.bi[c],        bhr = S.bh[c];
                const float biz = S.bi[c + 512],  bhz = S.bh[c + 512];
                const float bin = S.bi[c + 1024], bhn = S.bh[c + 1024];
                #pragma unroll
                for (int g = 0; g < GPB; g++) {
                    if (S.active[g]) {
                        const float r = sigmoidf_((ai[jr][g] + bir) + (ah[jr][g] + bhr));
                        const float z = sigmoidf_((ai[jz][g] + biz) + (ah[jz][g] + bhz));
                        const float n = tanhf((ai[jn][g] + bin) + r * (ah[jn][g] + bhn));
                        const float h = S.h[g][c];
                        S.h[g][c] = (1.0f - z) * n + z * h;
                    }
                }
            }
            __syncthreads();   // h stable before next step's emb
        }
        // if !anyact: h unchanged; next iteration's __syncthreads_or is the barrier
    }
}

extern "C" void kernel_launch(void* const* d_in, const int* in_sizes, int n_in,
                              void* d_out, int out_size) {
    const int*   actions      = (const int*)  d_in[0];
    const float* edge_tokens  = (const float*)d_in[1];
    const int*   stop_indices = (const int*)  d_in[2];
    const float* question     = (const float*)d_in[3];
    const float* node_tokens  = (const float*)d_in[4];
    const int*   start_locals = (const int*)  d_in[5];
    const int*   start_ptr    = (const int*)  d_in[6];
    const float* w_ih         = (const float*)d_in[7];
    const float* w_hh         = (const float*)d_in[8];
    const float* b_ih         = (const float*)d_in[9];
    const float* b_hh         = (const float*)d_in[10];
    const float* ln_w         = (const float*)d_in[11];
    const float* ln_b         = (const float*)d_in[12];
    float*       out          = (float*)d_out;

    const size_t smem_bytes = sizeof(Smem);
    cudaFuncSetAttribute(traj_encoder_kernel,
                         cudaFuncAttributeMaxDynamicSharedMemorySize,
                         (int)smem_bytes);

    traj_encoder_kernel<<<NBLOCKS, NTHREADS, smem_bytes>>>(
        actions, edge_tokens, stop_indices, question, node_tokens,
        start_locals, start_ptr, w_ih, w_hh, b_ih, b_hh, ln_w, ln_b, out);
}

// round 12
// speedup vs baseline: 1.1746x; 1.1746x over previous
#include <cuda_runtime.h>
#include <math.h>

#define BGRAPHS 1024
#define TSTEPS  64
#define HDIM    512
#define H3      1536
#define EEDGES  200000

#define NCTAS   128
#define NTH_S   512            // step-kernel threads
#define CPB     4              // channels per CTA (512/128)
#define ROWS    12             // 3 gates * CPB
#define KC      8              // k-chunk
#define NCHUNK  (HDIM / KC)    // 64

// Persistent state (ping-pong across the 64 step launches; re-initialized by
// init_kernel at the start of every graph replay -> deterministic).
__device__ float g_hT[2][HDIM * BGRAPHS];   // transposed h: [buf][k][b]
__device__ int   g_done[2][BGRAPHS];

__device__ __forceinline__ float warp_sum(float v) {
    #pragma unroll
    for (int o = 16; o > 0; o >>= 1) v += __shfl_xor_sync(0xFFFFFFFFu, v, o);
    return v;
}
__device__ __forceinline__ float sigmoidf_(float x) { return 1.0f / (1.0f + expf(-x)); }

// ---- packed fp32x2 helpers ----
__device__ __forceinline__ unsigned long long pack2(float lo, float hi) {
    unsigned long long r;
    asm("mov.b64 %0, {%1, %2};" : "=l"(r) : "f"(lo), "f"(hi));
    return r;
}
__device__ __forceinline__ void unpack2(unsigned long long v, float& lo, float& hi) {
    asm("mov.b64 {%0, %1}, %2;" : "=f"(lo), "=f"(hi) : "l"(v));
}
__device__ __forceinline__ void fma2(unsigned long long& acc,
                                     unsigned long long w2,
                                     unsigned long long a2) {
    asm("fma.rn.f32x2 %0, %1, %2, %0;" : "+l"(acc) : "l"(w2), "l"(a2));
}

// ---- cp.async helpers ----
__device__ __forceinline__ void cpasync16(void* smem_dst, const void* gsrc) {
    unsigned u = (unsigned)__cvta_generic_to_shared(smem_dst);
    asm volatile("cp.async.cg.shared.global [%0], [%1], 16;"
                 :: "r"(u), "l"(gsrc) : "memory");
}
__device__ __forceinline__ void cpasync_commit() {
    asm volatile("cp.async.commit_group;" ::: "memory");
}
template <int N>
__device__ __forceinline__ void cpasync_wait() {
    asm volatile("cp.async.wait_group %0;" :: "n"(N) : "memory");
}

// ============ init: h0 = LN(question + segmean(node_tokens)), done = 0 ============
__global__ void __launch_bounds__(256, 1)
init_kernel(const float* __restrict__ question,
            const float* __restrict__ node_tokens,
            const int*   __restrict__ start_locals,
            const int*   __restrict__ start_ptr,
            const float* __restrict__ ln_w,
            const float* __restrict__ ln_b)
{
    const int tid = threadIdx.x, wid = tid >> 5, lane = tid & 31;
    const int b = blockIdx.x * 8 + wid;

    const int p0 = start_ptr[b], p1 = start_ptr[b + 1];
    const int cnt = p1 - p0;
    const float inv_den = 1.0f / (float)(cnt > 0 ? cnt : 1);
    float v[16];
    #pragma unroll
    for (int i = 0; i < 16; i++) {
        const int c = lane + 32 * i;
        float s = 0.0f;
        for (int p = p0; p < p1; p++) {
            int node = start_locals[p];
            s += node_tokens[(size_t)node * HDIM + c];
        }
        v[i] = question[(size_t)b * HDIM + c] + s * inv_den;
    }
    float s = 0.0f;
    #pragma unroll
    for (int i = 0; i < 16; i++) s += v[i];
    s = warp_sum(s);
    const float m = s * (1.0f / HDIM);
    float q = 0.0f;
    #pragma unroll
    for (int i = 0; i < 16; i++) { float d = v[i] - m; q += d * d; }
    q = warp_sum(q);
    const float inv = rsqrtf(q * (1.0f / HDIM) + 1e-5f);
    #pragma unroll
    for (int i = 0; i < 16; i++) {
        const int c = lane + 32 * i;
        g_hT[0][(size_t)c * BGRAPHS + b] = (v[i] - m) * inv * ln_w[c] + ln_b[c];
    }
    if (tid < 8) g_done[0][blockIdx.x * 8 + tid] = 0;
}

// ============ one GRU step (launched 64x) ============
// CTA owns channels c0..c0+3 (gate rows c, 512+c, 1024+c) for ALL 1024 graphs.
// Thread p owns graph pair (p, p+512) packed into FFMA2 lanes.
__global__ void __launch_bounds__(NTH_S, 1)
step_kernel(const int*   __restrict__ actions,      // [B,T]
            const float* __restrict__ edge_tokens,  // [E,H]
            const int*   __restrict__ stop_indices, // [B]
            const float* __restrict__ w_ih,         // [3H,H]
            const float* __restrict__ w_hh,         // [3H,H]
            const float* __restrict__ b_ih,         // [3H]
            const float* __restrict__ b_hh,         // [3H]
            const float* __restrict__ ln_w,         // [H]
            const float* __restrict__ ln_b,         // [H]
            float*       __restrict__ out,          // [B,T,H]
            int t)
{
    extern __shared__ char sraw[];
    // layout: wsp_ih (48KB dup) | wsp_hh (48KB dup) | hbuf (64KB, 2 chunks) | ln (4KB)
    unsigned long long* wsp_ih = (unsigned long long*)sraw;                 // [ROWS*HDIM]
    unsigned long long* wsp_hh = wsp_ih + ROWS * HDIM;                      // [ROWS*HDIM]
    float* hbuf  = (float*)(wsp_hh + ROWS * HDIM);                          // [2][KC][BGRAPHS]
    float* lnw_s = hbuf + 2 * KC * BGRAPHS;
    float* lnb_s = lnw_s + HDIM;
    // raw weight staging aliases the hbuf area (freed before chunk 0 is staged)
    float* raw_ih = hbuf;                   // [ROWS*HDIM] = 24KB
    float* raw_hh = hbuf + ROWS * HDIM;     // next 24KB

    const int tid = threadIdx.x;
    const int cta = blockIdx.x;
    const int c0  = cta * CPB;

    const float* h_in   = g_hT[t & 1];
    float*       h_out  = g_hT[(t + 1) & 1];
    const int*   done_i = g_done[t & 1];
    int*         done_o = g_done[(t + 1) & 1];

    // ---- stage raw weight slices (12 rows x 512 each matrix) ----
    #pragma unroll
    for (int r = 0; r < 3; r++) {
        int piece = tid + NTH_S * r;          // 0..1535 (12 rows * 128 float4)
        int j = piece >> 7;
        int q = piece & 127;
        int gr = (j >> 2) * HDIM + c0 + (j & 3);   // j<4: r-rows, 4..7: z, 8..11: n
        cpasync16(raw_ih + j * HDIM + 4 * q, w_ih + (size_t)gr * HDIM + 4 * q);
        cpasync16(raw_hh + j * HDIM + 4 * q, w_hh + (size_t)gr * HDIM + 4 * q);
    }
    for (int i = tid; i < HDIM; i += NTH_S) { lnw_s[i] = ln_w[i]; lnb_s[i] = ln_b[i]; }
    cpasync_commit();

    // ---- per-thread graph pair ----
    const int b0 = tid, b1 = tid + 512;
    const int a0 = actions[(size_t)b0 * TSTEPS + t];
    const int a1 = actions[(size_t)b1 * TSTEPS + t];
    const bool act0 = (!done_i[b0]) && !((a0 < 0) || (a0 == stop_indices[b0]));
    const bool act1 = (!done_i[b1]) && !((a1 < 0) || (a1 == stop_indices[b1]));
    int i0 = a0 < 0 ? 0 : (a0 > EEDGES - 1 ? EEDGES - 1 : a0);
    int i1 = a1 < 0 ? 0 : (a1 > EEDGES - 1 ? EEDGES - 1 : a1);
    const float4* x0 = (const float4*)(edge_tokens + (size_t)i0 * HDIM);
    const float4* x1 = (const float4*)(edge_tokens + (size_t)i1 * HDIM);

    cpasync_wait<0>();
    __syncthreads();          // raw weights visible

    // ---- expand raw -> duplicated packed weights ----
    #pragma unroll
    for (int r = 0; r < ROWS * HDIM / NTH_S; r++) {   // 12 iters
        int i = tid + NTH_S * r;
        float wi = raw_ih[i];
        float wh = raw_hh[i];
        unsigned long long pwi = pack2(wi, wi);
        unsigned long long pwh = pack2(wh, wh);
        __syncthreads();      // (cheap correctness: read before overwrite round)
        wsp_ih[i] = pwi;
        wsp_hh[i] = pwh;
    }
    __syncthreads();          // wsp ready, hbuf area free

    // ---- stage h chunk 0 ----
    {
        #pragma unroll
        for (int r = 0; r < 4; r++) {
            int piece = tid + NTH_S * r;      // 0..2047
            int kk = piece >> 8;
            int q  = piece & 255;
            cpasync16(hbuf + kk * BGRAPHS + 4 * q,
                      h_in + (size_t)kk * BGRAPHS + 4 * q);
        }
        cpasync_commit();
    }

    unsigned long long acci[ROWS], acch[ROWS];
    #pragma unroll
    for (int j = 0; j < ROWS; j++) { acci[j] = 0ull; acch[j] = 0ull; }

    // ---- mainloop over k chunks ----
    #pragma unroll 1
    for (int c = 0; c < NCHUNK; c++) {
        const int k0  = c * KC;
        const int buf = c & 1;
        __syncthreads();                       // protect buf^1 (WAR)
        if (c + 1 < NCHUNK) {
            float* dst = hbuf + (buf ^ 1) * KC * BGRAPHS;
            #pragma unroll
            for (int r = 0; r < 4; r++) {
                int piece = tid + NTH_S * r;
                int kk = piece >> 8;
                int q  = piece & 255;
                cpasync16(dst + kk * BGRAPHS + 4 * q,
                          h_in + (size_t)(k0 + KC + kk) * BGRAPHS + 4 * q);
            }
            cpasync_commit();
            cpasync_wait<1>();                 // chunk c landed
        } else {
            cpasync_wait<0>();
        }
        __syncthreads();                       // chunk c visible

        const float4 xa0 = x0[(k0 >> 2)],     xb0 = x0[(k0 >> 2) + 1];
        const float4 xa1 = x1[(k0 >> 2)],     xb1 = x1[(k0 >> 2) + 1];
        const float* hc = hbuf + buf * KC * BGRAPHS;

        #pragma unroll
        for (int k4 = 0; k4 < 2; k4++) {
            unsigned long long hp[4], xp[4];
            #pragma unroll
            for (int u = 0; u < 4; u++) {
                int kk = k4 * 4 + u;
                hp[u] = pack2(hc[kk * BGRAPHS + b0], hc[kk * BGRAPHS + b1]);
                float xc0 = (k4 == 0)
                    ? ((u == 0) ? xa0.x : (u == 1) ? xa0.y : (u == 2) ? xa0.z : xa0.w)
                    : ((u == 0) ? xb0.x : (u == 1) ? xb0.y : (u == 2) ? xb0.z : xb0.w);
                float xc1 = (k4 == 0)
                    ? ((u == 0) ? xa1.x : (u == 1) ? xa1.y : (u == 2) ? xa1.z : xa1.w)
                    : ((u == 0) ? xb1.x : (u == 1) ? xb1.y : (u == 2) ? xb1.z : xb1.w);
                xp[u] = pack2(xc0, xc1);
            }
            #pragma unroll
            for (int j = 0; j < ROWS; j++) {
                const ulonglong2* wiv =
                    (const ulonglong2*)(wsp_ih + j * HDIM + k0 + k4 * 4);
                const ulonglong2* whv =
                    (const ulonglong2*)(wsp_hh + j * HDIM + k0 + k4 * 4);
                ulonglong2 wi0 = wiv[0], wi1 = wiv[1];
                ulonglong2 wh0 = whv[0], wh1 = whv[1];
                fma2(acci[j], wi0.x, xp[0]);
                fma2(acci[j], wi0.y, xp[1]);
                fma2(acci[j], wi1.x, xp[2]);
                fma2(acci[j], wi1.y, xp[3]);
                fma2(acch[j], wh0.x, hp[0]);
                fma2(acch[j], wh0.y, hp[1]);
                fma2(acch[j], wh1.x, hp[2]);
                fma2(acch[j], wh1.y, hp[3]);
            }
        }
    }

    // ---- epilogue: GRU update for channels c0..c0+3, graphs b0 and b1 ----
    {
        float fi[ROWS][2], fh[ROWS][2];
        #pragma unroll
        for (int j = 0; j < ROWS; j++) {
            unpack2(acci[j], fi[j][0], fi[j][1]);
            unpack2(acch[j], fh[j][0], fh[j][1]);
        }
        const int   bb[2]  = { b0, b1 };
        const bool  aa[2]  = { act0, act1 };
        #pragma unroll
        for (int s = 0; s < 2; s++) {
            const int b = bb[s];
            #pragma unroll
            for (int ch = 0; ch < CPB; ch++) {
                const int c = c0 + ch;
                const float hin = h_in[(size_t)c * BGRAPHS + b];
                float hn;
                if (aa[s]) {
                    const float r = sigmoidf_((fi[ch][s]     + b_ih[c])
                                            + (fh[ch][s]     + b_hh[c]));
                    const float z = sigmoidf_((fi[4 + ch][s] + b_ih[512 + c])
                                            + (fh[4 + ch][s] + b_hh[512 + c]));
                    const float n = tanhf((fi[8 + ch][s] + b_ih[1024 + c])
                                        + r * (fh[8 + ch][s] + b_hh[1024 + c]));
                    hn = (1.0f - z) * n + z * hin;
                } else {
                    hn = hin;
                }
                h_out[(size_t)c * BGRAPHS + b] = hn;
            }
        }
    }

    // ---- emb = LN(h_in) for this CTA's 8 owned graphs + done update ----
    if (tid < 256) {
        const int wid = tid >> 5, lane = tid & 31;
        const int gb = cta * 8 + wid;
        float v[16];
        #pragma unroll
        for (int i = 0; i < 16; i++)
            v[i] = h_in[(size_t)(lane + 32 * i) * BGRAPHS + gb];
        float s = 0.0f;
        #pragma unroll
        for (int i = 0; i < 16; i++) s += v[i];
        s = warp_sum(s);
        const float m = s * (1.0f / HDIM);
        float q = 0.0f;
        #pragma unroll
        for (int i = 0; i < 16; i++) { float d = v[i] - m; q += d * d; }
        q = warp_sum(q);
        const float inv = rsqrtf(q * (1.0f / HDIM) + 1e-5f);
        float* o = out + ((size_t)gb * TSTEPS + t) * HDIM;
        #pragma unroll
        for (int i = 0; i < 16; i++) {
            const int c = lane + 32 * i;
            o[c] = (v[i] - m) * inv * lnw_s[c] + lnb_s[c];
        }
        if (lane == 0) {
            const int a = actions[(size_t)gb * TSTEPS + t];
            const int isstop = (a < 0) || (a == stop_indices[gb]);
            done_o[gb] = done_i[gb] | isstop;
        }
    }
}

extern "C" void kernel_launch(void* const* d_in, const int* in_sizes, int n_in,
                              void* d_out, int out_size) {
    const int*   actions      = (const int*)  d_in[0];
    const float* edge_tokens  = (const float*)d_in[1];
    const int*   stop_indices = (const int*)  d_in[2];
    const float* question     = (const float*)d_in[3];
    const float* node_tokens  = (const float*)d_in[4];
    const int*   start_locals = (const int*)  d_in[5];
    const int*   start_ptr    = (const int*)  d_in[6];
    const float* w_ih         = (const float*)d_in[7];
    const float* w_hh         = (const float*)d_in[8];
    const float* b_ih         = (const float*)d_in[9];
    const float* b_hh         = (const float*)d_in[10];
    const float* ln_w         = (const float*)d_in[11];
    const float* ln_b         = (const float*)d_in[12];
    float*       out          = (float*)d_out;

    // SMEM: 2 * 48KB packed weights + 64KB h double-buffer + 4KB LN
    const size_t smem = (size_t)(2 * ROWS * HDIM) * 8 +
                        (size_t)(2 * KC * BGRAPHS) * 4 +
                        (size_t)(2 * HDIM) * 4;
    cudaFuncSetAttribute(step_kernel,
                         cudaFuncAttributeMaxDynamicSharedMemorySize, (int)smem);

    init_kernel<<<NCTAS, 256>>>(question, node_tokens, start_locals, start_ptr,
                                ln_w, ln_b);
    for (int t = 0; t < TSTEPS; t++) {
        step_kernel<<<NCTAS, NTH_S, smem>>>(actions, edge_tokens, stop_indices,
                                            w_ih, w_hh, b_ih, b_hh, ln_w, ln_b,
                                            out, t);
    }
}

// round 13
// speedup vs baseline: 1.6421x; 1.3980x over previous
#include <cuda_runtime.h>
#include <math.h>

#define BGRAPHS 1024
#define TSTEPS  64
#define HDIM    512
#define H3      1536
#define EEDGES  200000

#define NCTAS   128
#define NTH_S   512            // step-kernel threads
#define CPB     4              // channels per CTA (512/128)
#define ROWS    12             // 3 gates * CPB
#define KC      4              // k-chunk
#define NCHUNK  (HDIM / KC)    // 128

// Persistent scratch (re-initialized every replay -> deterministic)
__device__ float g_hT[2][HDIM * BGRAPHS];            // transposed h: [buf][k][b]
__device__ int   g_done[2][BGRAPHS];
__device__ float g_xT[TSTEPS][HDIM][BGRAPHS];        // gathered+transposed x (134MB)

__device__ __forceinline__ float warp_sum(float v) {
    #pragma unroll
    for (int o = 16; o > 0; o >>= 1) v += __shfl_xor_sync(0xFFFFFFFFu, v, o);
    return v;
}
__device__ __forceinline__ float sigmoidf_(float x) { return 1.0f / (1.0f + expf(-x)); }

// ---- packed fp32x2 helpers ----
__device__ __forceinline__ unsigned long long pack2(float lo, float hi) {
    unsigned long long r;
    asm("mov.b64 %0, {%1, %2};" : "=l"(r) : "f"(lo), "f"(hi));
    return r;
}
__device__ __forceinline__ void unpack2(unsigned long long v, float& lo, float& hi) {
    asm("mov.b64 {%0, %1}, %2;" : "=f"(lo), "=f"(hi) : "l"(v));
}
__device__ __forceinline__ void fma2(unsigned long long& acc,
                                     unsigned long long w2,
                                     unsigned long long a2) {
    asm("fma.rn.f32x2 %0, %1, %2, %0;" : "+l"(acc) : "l"(w2), "l"(a2));
}

// ---- cp.async helpers ----
__device__ __forceinline__ void cpasync16(void* smem_dst, const void* gsrc) {
    unsigned u = (unsigned)__cvta_generic_to_shared(smem_dst);
    asm volatile("cp.async.cg.shared.global [%0], [%1], 16;"
                 :: "r"(u), "l"(gsrc) : "memory");
}
__device__ __forceinline__ void cpasync_commit() {
    asm volatile("cp.async.commit_group;" ::: "memory");
}
template <int N>
__device__ __forceinline__ void cpasync_wait() {
    asm volatile("cp.async.wait_group %0;" :: "n"(N) : "memory");
}

// ============ init: h0 = LN(question + segmean(node_tokens)), done = 0 ============
__global__ void __launch_bounds__(256, 1)
init_kernel(const float* __restrict__ question,
            const float* __restrict__ node_tokens,
            const int*   __restrict__ start_locals,
            const int*   __restrict__ start_ptr,
            const float* __restrict__ ln_w,
            const float* __restrict__ ln_b)
{
    const int tid = threadIdx.x, wid = tid >> 5, lane = tid & 31;
    const int b = blockIdx.x * 8 + wid;

    const int p0 = start_ptr[b], p1 = start_ptr[b + 1];
    const int cnt = p1 - p0;
    const float inv_den = 1.0f / (float)(cnt > 0 ? cnt : 1);
    float v[16];
    #pragma unroll
    for (int i = 0; i < 16; i++) {
        const int c = lane + 32 * i;
        float s = 0.0f;
        for (int p = p0; p < p1; p++) {
            int node = start_locals[p];
            s += node_tokens[(size_t)node * HDIM + c];
        }
        v[i] = question[(size_t)b * HDIM + c] + s * inv_den;
    }
    float s = 0.0f;
    #pragma unroll
    for (int i = 0; i < 16; i++) s += v[i];
    s = warp_sum(s);
    const float m = s * (1.0f / HDIM);
    float q = 0.0f;
    #pragma unroll
    for (int i = 0; i < 16; i++) { float d = v[i] - m; q += d * d; }
    q = warp_sum(q);
    const float inv = rsqrtf(q * (1.0f / HDIM) + 1e-5f);
    #pragma unroll
    for (int i = 0; i < 16; i++) {
        const int c = lane + 32 * i;
        g_hT[0][(size_t)c * BGRAPHS + b] = (v[i] - m) * inv * ln_w[c] + ln_b[c];
    }
    if (tid < 8) g_done[0][blockIdx.x * 8 + tid] = 0;
}

// ============ gather + transpose x for ALL steps: g_xT[t][k][b] ============
// grid (32 b-tiles, 16 k-tiles, 64 t), block (32,8). Coalesced both directions.
__global__ void __launch_bounds__(256, 4)
xpose_kernel(const int* __restrict__ actions,
             const float* __restrict__ edge_tokens)
{
    __shared__ float tile[32][33];
    __shared__ int   sidx[32];
    const int tx = threadIdx.x, ty = threadIdx.y;
    const int b0 = blockIdx.x * 32, k0 = blockIdx.y * 32, t = blockIdx.z;

    if (ty == 0) {
        int a = actions[(size_t)(b0 + tx) * TSTEPS + t];
        int i = a < 0 ? 0 : (a > EEDGES - 1 ? EEDGES - 1 : a);
        sidx[tx] = i;
    }
    __syncthreads();
    #pragma unroll
    for (int i = 0; i < 4; i++) {
        const int bl = ty + 8 * i;
        tile[tx][bl] = edge_tokens[(size_t)sidx[bl] * HDIM + k0 + tx];
    }
    __syncthreads();
    #pragma unroll
    for (int i = 0; i < 4; i++) {
        const int kl = ty + 8 * i;
        g_xT[t][k0 + kl][b0 + tx] = tile[kl][tx];
    }
}

// ============ one GRU step (launched 64x) ============
// CTA owns channels c0..c0+3 (gate rows c, 512+c, 1024+c) for ALL 1024 graphs.
// Thread p owns graph pair (p, p+512) packed into FFMA2 lanes.
__global__ void __launch_bounds__(NTH_S, 1)
step_kernel(const int*   __restrict__ actions,
            const float* __restrict__ stop_f_unused,
            const int*   __restrict__ stop_indices,
            const float* __restrict__ w_ih,
            const float* __restrict__ w_hh,
            const float* __restrict__ b_ih,
            const float* __restrict__ b_hh,
            const float* __restrict__ ln_w,
            const float* __restrict__ ln_b,
            float*       __restrict__ out,
            int t)
{
    extern __shared__ char sraw[];
    // layout: wsp_ih (48KB dup) | wsp_hh (48KB dup) | stage (64KB: 2 bufs x [h(16KB)+x(16KB)]) | ln (4KB)
    unsigned long long* wsp_ih = (unsigned long long*)sraw;          // [ROWS*HDIM]
    unsigned long long* wsp_hh = wsp_ih + ROWS * HDIM;               // [ROWS*HDIM]
    float* stage = (float*)(wsp_hh + ROWS * HDIM);                   // [2][2*KC*BGRAPHS]
    float* lnw_s = stage + 2 * (2 * KC * BGRAPHS);
    float* lnb_s = lnw_s + HDIM;
    // raw weight staging aliases the stage area (freed before chunk 0 staged)
    float* raw_ih = stage;                    // 24KB
    float* raw_hh = stage + ROWS * HDIM;      // next 24KB

    const int tid = threadIdx.x;
    const int cta = blockIdx.x;
    const int c0  = cta * CPB;

    const float* h_in   = g_hT[t & 1];
    float*       h_out  = g_hT[(t + 1) & 1];
    const int*   done_i = g_done[t & 1];
    int*         done_o = g_done[(t + 1) & 1];
    const float* xt     = &g_xT[t][0][0];

    // ---- stage raw weight slices (12 rows x 512 each matrix) ----
    #pragma unroll
    for (int r = 0; r < 3; r++) {
        int piece = tid + NTH_S * r;          // 0..1535
        int j = piece >> 7;
        int q = piece & 127;
        int gr = (j >> 2) * HDIM + c0 + (j & 3);
        cpasync16(raw_ih + j * HDIM + 4 * q, w_ih + (size_t)gr * HDIM + 4 * q);
        cpasync16(raw_hh + j * HDIM + 4 * q, w_hh + (size_t)gr * HDIM + 4 * q);
    }
    for (int i = tid; i < HDIM; i += NTH_S) { lnw_s[i] = ln_w[i]; lnb_s[i] = ln_b[i]; }
    cpasync_commit();

    // ---- per-thread graph-pair flags (no x pointers anymore) ----
    const int b0 = tid, b1 = tid + 512;
    const int a0 = actions[(size_t)b0 * TSTEPS + t];
    const int a1 = actions[(size_t)b1 * TSTEPS + t];
    const bool act0 = (!done_i[b0]) && !((a0 < 0) || (a0 == stop_indices[b0]));
    const bool act1 = (!done_i[b1]) && !((a1 < 0) || (a1 == stop_indices[b1]));

    cpasync_wait<0>();
    __syncthreads();          // raw weights visible

    // ---- expand raw -> duplicated packed weights (disjoint regions) ----
    #pragma unroll
    for (int r = 0; r < ROWS * HDIM / NTH_S; r++) {   // 12 iters
        int i = tid + NTH_S * r;
        float wi = raw_ih[i];
        float wh = raw_hh[i];
        wsp_ih[i] = pack2(wi, wi);
        wsp_hh[i] = pack2(wh, wh);
    }
    __syncthreads();          // wsp ready, stage area free

    // ---- stage chunk 0 (h then x halves) ----
    {
        float* dst = stage;
        #pragma unroll
        for (int r = 0; r < 8; r++) {
            int piece = tid + NTH_S * r;      // 0..4095
            if (piece < 1024) {
                int kk = piece >> 8, q = piece & 255;
                cpasync16(dst + kk * BGRAPHS + 4 * q,
                          h_in + (size_t)kk * BGRAPHS + 4 * q);
            } else if (piece < 2048) {
                int p2 = piece - 1024;
                int kk = p2 >> 8, q = p2 & 255;
                cpasync16(dst + KC * BGRAPHS + kk * BGRAPHS + 4 * q,
                          xt + (size_t)kk * BGRAPHS + 4 * q);
            }
        }
        cpasync_commit();
    }

    unsigned long long acci[ROWS], acch[ROWS];
    #pragma unroll
    for (int j = 0; j < ROWS; j++) { acci[j] = 0ull; acch[j] = 0ull; }

    // ---- mainloop over 128 k-chunks ----
    #pragma unroll 1
    for (int c = 0; c < NCHUNK; c++) {
        const int k0  = c * KC;
        const int buf = c & 1;
        __syncthreads();                       // WAR on buf^1
        if (c + 1 < NCHUNK) {
            float* dst = stage + (buf ^ 1) * (2 * KC * BGRAPHS);
            const int kn = k0 + KC;
            #pragma unroll
            for (int r = 0; r < 8; r++) {
                int piece = tid + NTH_S * r;
                if (piece < 1024) {
                    int kk = piece >> 8, q = piece & 255;
                    cpasync16(dst + kk * BGRAPHS + 4 * q,
                              h_in + (size_t)(kn + kk) * BGRAPHS + 4 * q);
                } else if (piece < 2048) {
                    int p2 = piece - 1024;
                    int kk = p2 >> 8, q = p2 & 255;
                    cpasync16(dst + KC * BGRAPHS + kk * BGRAPHS + 4 * q,
                              xt + (size_t)(kn + kk) * BGRAPHS + 4 * q);
                }
            }
            cpasync_commit();
            cpasync_wait<1>();                 // chunk c landed
        } else {
            cpasync_wait<0>();
        }
        __syncthreads();                       // chunk c visible

        const float* hc = stage + buf * (2 * KC * BGRAPHS);
        const float* xc = hc + KC * BGRAPHS;

        unsigned long long hp[KC], xp[KC];
        #pragma unroll
        for (int u = 0; u < KC; u++) {
            hp[u] = pack2(hc[u * BGRAPHS + b0], hc[u * BGRAPHS + b1]);
            xp[u] = pack2(xc[u * BGRAPHS + b0], xc[u * BGRAPHS + b1]);
        }
        #pragma unroll
        for (int j = 0; j < ROWS; j++) {
            const ulonglong2* wiv = (const ulonglong2*)(wsp_ih + j * HDIM + k0);
            const ulonglong2* whv = (const ulonglong2*)(wsp_hh + j * HDIM + k0);
            ulonglong2 wi0 = wiv[0], wi1 = wiv[1];
            ulonglong2 wh0 = whv[0], wh1 = whv[1];
            fma2(acci[j], wi0.x, xp[0]);
            fma2(acci[j], wi0.y, xp[1]);
            fma2(acci[j], wi1.x, xp[2]);
            fma2(acci[j], wi1.y, xp[3]);
            fma2(acch[j], wh0.x, hp[0]);
            fma2(acch[j], wh0.y, hp[1]);
            fma2(acch[j], wh1.x, hp[2]);
            fma2(acch[j], wh1.y, hp[3]);
        }
    }

    // ---- epilogue: GRU update for channels c0..c0+3, graphs b0 and b1 ----
    {
        float fi[ROWS][2], fh[ROWS][2];
        #pragma unroll
        for (int j = 0; j < ROWS; j++) {
            unpack2(acci[j], fi[j][0], fi[j][1]);
            unpack2(acch[j], fh[j][0], fh[j][1]);
        }
        const int  bb[2] = { b0, b1 };
        const bool aa[2] = { act0, act1 };
        #pragma unroll
        for (int s = 0; s < 2; s++) {
            const int b = bb[s];
            #pragma unroll
            for (int ch = 0; ch < CPB; ch++) {
                const int c = c0 + ch;
                const float hin = h_in[(size_t)c * BGRAPHS + b];
                float hn;
                if (aa[s]) {
                    const float r = sigmoidf_((fi[ch][s]     + b_ih[c])
                                            + (fh[ch][s]     + b_hh[c]));
                    const float z = sigmoidf_((fi[4 + ch][s] + b_ih[512 + c])
                                            + (fh[4 + ch][s] + b_hh[512 + c]));
                    const float n = tanhf((fi[8 + ch][s] + b_ih[1024 + c])
                                        + r * (fh[8 + ch][s] + b_hh[1024 + c]));
                    hn = (1.0f - z) * n + z * hin;
                } else {
                    hn = hin;
                }
                h_out[(size_t)c * BGRAPHS + b] = hn;
            }
        }
    }

    // ---- emb = LN(h_in) for this CTA's 8 owned graphs + done update ----
    if (tid < 256) {
        const int wid = tid >> 5, lane = tid & 31;
        const int gb = cta * 8 + wid;
        float v[16];
        #pragma unroll
        for (int i = 0; i < 16; i++)
            v[i] = h_in[(size_t)(lane + 32 * i) * BGRAPHS + gb];
        float s = 0.0f;
        #pragma unroll
        for (int i = 0; i < 16; i++) s += v[i];
        s = warp_sum(s);
        const float m = s * (1.0f / HDIM);
        float q = 0.0f;
        #pragma unroll
        for (int i = 0; i < 16; i++) { float d = v[i] - m; q += d * d; }
        q = warp_sum(q);
        const float inv = rsqrtf(q * (1.0f / HDIM) + 1e-5f);
        float* o = out + ((size_t)gb * TSTEPS + t) * HDIM;
        #pragma unroll
        for (int i = 0; i < 16; i++) {
            const int c = lane + 32 * i;
            o[c] = (v[i] - m) * inv * lnw_s[c] + lnb_s[c];
        }
        if (lane == 0) {
            const int a = actions[(size_t)gb * TSTEPS + t];
            const int isstop = (a < 0) || (a == stop_indices[gb]);
            done_o[gb] = done_i[gb] | isstop;
        }
    }
}

extern "C" void kernel_launch(void* const* d_in, const int* in_sizes, int n_in,
                              void* d_out, int out_size) {
    const int*   actions      = (const int*)  d_in[0];
    const float* edge_tokens  = (const float*)d_in[1];
    const int*   stop_indices = (const int*)  d_in[2];
    const float* question     = (const float*)d_in[3];
    const float* node_tokens  = (const float*)d_in[4];
    const int*   start_locals = (const int*)  d_in[5];
    const int*   start_ptr    = (const int*)  d_in[6];
    const float* w_ih         = (const float*)d_in[7];
    const float* w_hh         = (const float*)d_in[8];
    const float* b_ih         = (const float*)d_in[9];
    const float* b_hh         = (const float*)d_in[10];
    const float* ln_w         = (const float*)d_in[11];
    const float* ln_b         = (const float*)d_in[12];
    float*       out          = (float*)d_out;

    // SMEM: 96KB packed weights + 64KB h/x double-buffer + 4KB LN = 164KB
    const size_t smem = (size_t)(2 * ROWS * HDIM) * 8 +
                        (size_t)(2 * 2 * KC * BGRAPHS) * 4 +
                        (size_t)(2 * HDIM) * 4;
    cudaFuncSetAttribute(step_kernel,
                         cudaFuncAttributeMaxDynamicSharedMemorySize, (int)smem);

    init_kernel<<<NCTAS, 256>>>(question, node_tokens, start_locals, start_ptr,
                                ln_w, ln_b);
    xpose_kernel<<<dim3(32, 16, 64), dim3(32, 8)>>>(actions, edge_tokens);
    for (int t = 0; t < TSTEPS; t++) {
        step_kernel<<<NCTAS, NTH_S, smem>>>(actions, nullptr, stop_indices,
                                            w_ih, w_hh, b_ih, b_hh, ln_w, ln_b,
                                            out, t);
    }
}

// round 16
// speedup vs baseline: 2.3459x; 1.4286x over previous
#include <cuda_runtime.h>
#include <math.h>

#define BGRAPHS 1024
#define TSTEPS  64
#define HDIM    512
#define H3      1536
#define EEDGES  200000

#define NCTAS   128
#define NTH_S   512
#define CPB     4              // channels per CTA

// Persistent scratch (re-initialized every replay -> deterministic)
__device__ float g_hT[2][HDIM * BGRAPHS];            // transposed h: [buf][k][b]
__device__ int   g_done[2][BGRAPHS];
__device__ float g_xT[TSTEPS][HDIM][BGRAPHS];        // gathered+transposed x

__device__ __forceinline__ float warp_sum(float v) {
    #pragma unroll
    for (int o = 16; o > 0; o >>= 1) v += __shfl_xor_sync(0xFFFFFFFFu, v, o);
    return v;
}
__device__ __forceinline__ float sigmoidf_(float x) { return 1.0f / (1.0f + expf(-x)); }

__device__ __forceinline__ unsigned long long pack2(float lo, float hi) {
    unsigned long long r;
    asm("mov.b64 %0, {%1, %2};" : "=l"(r) : "f"(lo), "f"(hi));
    return r;
}
__device__ __forceinline__ void unpack2(unsigned long long v, float& lo, float& hi) {
    asm("mov.b64 {%0, %1}, %2;" : "=f"(lo), "=f"(hi) : "l"(v));
}
__device__ __forceinline__ void fma2(unsigned long long& acc,
                                     unsigned long long w2,
                                     unsigned long long a2) {
    asm("fma.rn.f32x2 %0, %1, %2, %0;" : "+l"(acc) : "l"(w2), "l"(a2));
}

// ============ init: h0 = LN(question + segmean(node_tokens)), done = 0 ============
__global__ void __launch_bounds__(256, 1)
init_kernel(const float* __restrict__ question,
            const float* __restrict__ node_tokens,
            const int*   __restrict__ start_locals,
            const int*   __restrict__ start_ptr,
            const float* __restrict__ ln_w,
            const float* __restrict__ ln_b)
{
    const int tid = threadIdx.x, wid = tid >> 5, lane = tid & 31;
    const int b = blockIdx.x * 8 + wid;

    const int p0 = start_ptr[b], p1 = start_ptr[b + 1];
    const int cnt = p1 - p0;
    const float inv_den = 1.0f / (float)(cnt > 0 ? cnt : 1);
    float v[16];
    #pragma unroll
    for (int i = 0; i < 16; i++) {
        const int c = lane + 32 * i;
        float s = 0.0f;
        for (int p = p0; p < p1; p++) {
            int node = start_locals[p];
            s += node_tokens[(size_t)node * HDIM + c];
        }
        v[i] = question[(size_t)b * HDIM + c] + s * inv_den;
    }
    float s = 0.0f;
    #pragma unroll
    for (int i = 0; i < 16; i++) s += v[i];
    s = warp_sum(s);
    const float m = s * (1.0f / HDIM);
    float q = 0.0f;
    #pragma unroll
    for (int i = 0; i < 16; i++) { float d = v[i] - m; q += d * d; }
    q = warp_sum(q);
    const float inv = rsqrtf(q * (1.0f / HDIM) + 1e-5f);
    #pragma unroll
    for (int i = 0; i < 16; i++) {
        const int c = lane + 32 * i;
        g_hT[0][(size_t)c * BGRAPHS + b] = (v[i] - m) * inv * ln_w[c] + ln_b[c];
    }
    if (tid < 8) g_done[0][blockIdx.x * 8 + tid] = 0;
}

// ============ gather + transpose x for ALL steps: g_xT[t][k][b] ============
__global__ void __launch_bounds__(256, 4)
xpose_kernel(const int* __restrict__ actions,
             const float* __restrict__ edge_tokens)
{
    __shared__ float tile[32][33];
    __shared__ int   sidx[32];
    const int tx = threadIdx.x, ty = threadIdx.y;
    const int b0 = blockIdx.x * 32, k0 = blockIdx.y * 32, t = blockIdx.z;

    if (ty == 0) {
        int a = actions[(size_t)(b0 + tx) * TSTEPS + t];
        int i = a < 0 ? 0 : (a > EEDGES - 1 ? EEDGES - 1 : a);
        sidx[tx] = i;
    }
    __syncthreads();
    #pragma unroll
    for (int i = 0; i < 4; i++) {
        const int bl = ty + 8 * i;
        tile[tx][bl] = edge_tokens[(size_t)sidx[bl] * HDIM + k0 + tx];
    }
    __syncthreads();
    #pragma unroll
    for (int i = 0; i < 4; i++) {
        const int kl = ty + 8 * i;
        g_xT[t][k0 + kl][b0 + tx] = tile[kl][tx];
    }
}

// ============ one GRU step (launched 64x) ============
// CTA owns channels c0..c0+3 for ALL 1024 graphs.
// rg = tid>>8 owns channels {c0+2rg, c0+2rg+1}; q = tid&255 owns graphs 4q..4q+3.
// Mainloop: barrier-free, h/x direct LDG.128, weights broadcast LDS.64 from smem.
__global__ void __launch_bounds__(NTH_S, 1)
step_kernel(const int*   __restrict__ actions,
            const int*   __restrict__ stop_indices,
            const float* __restrict__ w_ih,
            const float* __restrict__ w_hh,
            const float* __restrict__ b_ih,
            const float* __restrict__ b_hh,
            const float* __restrict__ ln_w,
            const float* __restrict__ ln_b,
            float*       __restrict__ out,
            int t)
{
    extern __shared__ char sraw[];
    unsigned long long* wsp = (unsigned long long*)sraw;   // [24][512] packed (ih rows 0..11, hh 12..23)
    float* lnw_s = (float*)(wsp + 24 * HDIM);
    float* lnb_s = lnw_s + HDIM;

    const int tid = threadIdx.x;
    const int cta = blockIdx.x;
    const int c0  = cta * CPB;
    const int rg  = tid >> 8;          // 0..1
    const int q   = tid & 255;         // graph slot: graphs 4q..4q+3

    const float* h_in   = g_hT[t & 1];
    float*       h_out  = g_hT[(t + 1) & 1];
    const int*   done_i = g_done[t & 1];
    int*         done_o = g_done[(t + 1) & 1];
    const float* xt     = &g_xT[t][0][0];

    // ---- stage packed (duplicated) weights: rows j = gate*4 + chan, both mats ----
    #pragma unroll
    for (int r = 0; r < 24; r++) {
        int idx = tid + NTH_S * r;         // 0..12287
        int k   = idx & 511;
        int jm  = idx >> 9;                // 0..23
        int j   = jm % 12;
        int gr  = (j >> 2) * HDIM + c0 + (j & 3);
        const float* W = (jm < 12) ? w_ih : w_hh;
        float w = W[(size_t)gr * HDIM + k];
        wsp[(size_t)jm * HDIM + k] = pack2(w, w);
    }
    lnw_s[tid] = ln_w[tid];
    lnb_s[tid] = ln_b[tid];

    // ---- per-thread graph flags (4 graphs) ----
    bool act[4];
    #pragma unroll
    for (int i = 0; i < 4; i++) {
        int b = 4 * q + i;
        int a = actions[(size_t)b * TSTEPS + t];
        act[i] = (!done_i[b]) && !((a < 0) || (a == stop_indices[b]));
    }

    __syncthreads();   // weights + LN staged

    // ---- accumulators: [ch][gate][pair] ----
    unsigned long long acci[2][3][2], acch[2][3][2];
    #pragma unroll
    for (int ch = 0; ch < 2; ch++)
        #pragma unroll
        for (int g = 0; g < 3; g++)
            #pragma unroll
            for (int p = 0; p < 2; p++) { acci[ch][g][p] = 0ull; acch[ch][g][p] = 0ull; }

    const float* hrow = h_in + 4 * q;
    const float* xrow = xt + 4 * q;

    // ---- barrier-free mainloop over k ----
    #pragma unroll 1
    for (int kb = 0; kb < HDIM; kb += 4) {
        #pragma unroll
        for (int ku = 0; ku < 4; ku++) {
            const int k = kb + ku;
            const float4 h4 = *(const float4*)(hrow + (size_t)k * BGRAPHS);
            const float4 x4 = *(const float4*)(xrow + (size_t)k * BGRAPHS);
            unsigned long long hp[2], xp[2];
            hp[0] = pack2(h4.x, h4.y); hp[1] = pack2(h4.z, h4.w);
            xp[0] = pack2(x4.x, x4.y); xp[1] = pack2(x4.z, x4.w);
            #pragma unroll
            for (int ch = 0; ch < 2; ch++) {
                const int lr = 2 * rg + ch;
                #pragma unroll
                for (int g = 0; g < 3; g++) {
                    const unsigned long long wi = wsp[(size_t)(g * 4 + lr) * HDIM + k];
                    const unsigned long long wh = wsp[(size_t)(12 + g * 4 + lr) * HDIM + k];
                    fma2(acci[ch][g][0], wi, xp[0]);
                    fma2(acci[ch][g][1], wi, xp[1]);
                    fma2(acch[ch][g][0], wh, hp[0]);
                    fma2(acch[ch][g][1], wh, hp[1]);
                }
            }
        }
    }

    // ---- epilogue: GRU update for 2 channels x 4 graphs ----
    #pragma unroll
    for (int ch = 0; ch < 2; ch++) {
        const int c = c0 + 2 * rg + ch;
        const float bir = b_ih[c],        bhr = b_hh[c];
        const float biz = b_ih[512 + c],  bhz = b_hh[512 + c];
        const float bin = b_ih[1024 + c], bhn = b_hh[1024 + c];
        float fr[4], fz[4], fn[4], gr_[4], gz[4], gn[4];
        #pragma unroll
        for (int p = 0; p < 2; p++) {
            unpack2(acci[ch][0][p], fr[2*p],  fr[2*p+1]);
            unpack2(acci[ch][1][p], fz[2*p],  fz[2*p+1]);
            unpack2(acci[ch][2][p], fn[2*p],  fn[2*p+1]);
            unpack2(acch[ch][0][p], gr_[2*p], gr_[2*p+1]);
            unpack2(acch[ch][1][p], gz[2*p],  gz[2*p+1]);
            unpack2(acch[ch][2][p], gn[2*p],  gn[2*p+1]);
        }
        const float4 hi4 = *(const float4*)(h_in + (size_t)c * BGRAPHS + 4 * q);
        const float hin[4] = { hi4.x, hi4.y, hi4.z, hi4.w };
        float4 ho;
        float* hop = (float*)&ho;
        #pragma unroll
        for (int i = 0; i < 4; i++) {
            float hn;
            if (act[i]) {
                const float r = sigmoidf_((fr[i] + bir) + (gr_[i] + bhr));
                const float z = sigmoidf_((fz[i] + biz) + (gz[i] + bhz));
                const float n = tanhf((fn[i] + bin) + r * (gn[i] + bhn));
                hn = (1.0f - z) * n + z * hin[i];
            } else {
                hn = hin[i];
            }
            hop[i] = hn;
        }
        *(float4*)(h_out + (size_t)c * BGRAPHS + 4 * q) = ho;
    }

    // ---- emb = LN(h_in) for this CTA's 8 owned graphs + done update ----
    if (tid < 256) {
        const int wid = tid >> 5, lane = tid & 31;
        const int gb = cta * 8 + wid;
        float v[16];
        #pragma unroll
        for (int i = 0; i < 16; i++)
            v[i] = h_in[(size_t)(lane + 32 * i) * BGRAPHS + gb];
        float s = 0.0f;
        #pragma unroll
        for (int i = 0; i < 16; i++) s += v[i];
        s = warp_sum(s);
        const float m = s * (1.0f / HDIM);
        float qv = 0.0f;
        #pragma unroll
        for (int i = 0; i < 16; i++) { float d = v[i] - m; qv += d * d; }
        qv = warp_sum(qv);
        const float inv = rsqrtf(qv * (1.0f / HDIM) + 1e-5f);
        float* o = out + ((size_t)gb * TSTEPS + t) * HDIM;
        #pragma unroll
        for (int i = 0; i < 16; i++) {
            const int c = lane + 32 * i;
            o[c] = (v[i] - m) * inv * lnw_s[c] + lnb_s[c];
        }
        if (lane == 0) {
            const int a = actions[(size_t)gb * TSTEPS + t];
            const int isstop = (a < 0) || (a == stop_indices[gb]);
            done_o[gb] = done_i[gb] | isstop;
        }
    }
}

extern "C" void kernel_launch(void* const* d_in, const int* in_sizes, int n_in,
                              void* d_out, int out_size) {
    const int*   actions      = (const int*)  d_in[0];
    const float* edge_tokens  = (const float*)d_in[1];
    const int*   stop_indices = (const int*)  d_in[2];
    const float* question     = (const float*)d_in[3];
    const float* node_tokens  = (const float*)d_in[4];
    const int*   start_locals = (const int*)  d_in[5];
    const int*   start_ptr    = (const int*)  d_in[6];
    const float* w_ih         = (const float*)d_in[7];
    const float* w_hh         = (const float*)d_in[8];
    const float* b_ih         = (const float*)d_in[9];
    const float* b_hh         = (const float*)d_in[10];
    const float* ln_w         = (const float*)d_in[11];
    const float* ln_b         = (const float*)d_in[12];
    float*       out          = (float*)d_out;

    // SMEM: 96KB packed weights + 4KB LN
    const size_t smem = (size_t)(24 * HDIM) * 8 + (size_t)(2 * HDIM) * 4;
    cudaFuncSetAttribute(step_kernel,
                         cudaFuncAttributeMaxDynamicSharedMemorySize, (int)smem);

    init_kernel<<<NCTAS, 256>>>(question, node_tokens, start_locals, start_ptr,
                                ln_w, ln_b);
    xpose_kernel<<<dim3(32, 16, 64), dim3(32, 8)>>>(actions, edge_tokens);
    for (int t = 0; t < TSTEPS; t++) {
        step_kernel<<<NCTAS, NTH_S, smem>>>(actions, stop_indices,
                                            w_ih, w_hh, b_ih, b_hh, ln_w, ln_b,
                                            out, t);
    }
}